// round 15
// baseline (speedup 1.0000x reference)
#include <cuda_runtime.h>
#include <cstdint>

#define B_SZ 8
#define SEQ 4096
#define DM 1024
#define DS 64
#define LTAPS 64

#define TBLK 128   // time steps per block
#define CBLK 64    // channels per block (32 float2 pairs)
#define TT 8       // outputs per thread
#define NTHR 512   // conv block size
#define G 8        // tap group size

__device__ float g_K[LTAPS * DM];   // K[l][c], channel-contiguous

// ---------------- packed f32x2 ops (Blackwell FFMA2, PTX-only) ----------------

__device__ __forceinline__ float2 ffma2(float2 a, float2 b, float2 c) {
    float2 d;
    asm("fma.rn.f32x2 %0, %1, %2, %3;"
        : "=l"(*reinterpret_cast<unsigned long long*>(&d))
        : "l"(*reinterpret_cast<const unsigned long long*>(&a)),
          "l"(*reinterpret_cast<const unsigned long long*>(&b)),
          "l"(*reinterpret_cast<const unsigned long long*>(&c)));
    return d;
}

__device__ __forceinline__ float2 fmul2(float2 a, float2 b) {
    float2 d;
    asm("mul.rn.f32x2 %0, %1, %2;"
        : "=l"(*reinterpret_cast<unsigned long long*>(&d))
        : "l"(*reinterpret_cast<const unsigned long long*>(&a)),
          "l"(*reinterpret_cast<const unsigned long long*>(&b)));
    return d;
}

// ---------------- fused prep: Csum (parallel, coalesced) + K build ------------
// grid 16 x block 1024. Phase A: 16 slices x 64 cols, 64 coalesced loads/thread,
// smem reduce. Phase B: threads 0..63 build K for 64 channels (f32x2 chains,
// 4 independent d-chains in flight).
__global__ __launch_bounds__(1024)
void prep_kernel(const float* __restrict__ A,
                 const float* __restrict__ Bp,
                 const float* __restrict__ C,
                 const float* __restrict__ log_dt) {
    __shared__ float sh_part[16][DS];
    __shared__ float sh_csum[DS];

    const int tid = threadIdx.x;
    const int d   = tid & 63;
    const int s   = tid >> 6;    // slice 0..15, rows [64s, 64s+64)

    // phase A: partial column sums, fully coalesced (64 consecutive threads ->
    // 64 consecutive addresses), 8-way MLP
    {
        const float* __restrict__ Cp = C + (size_t)(s * 64) * DS + d;
        float acc = 0.f;
        #pragma unroll 8
        for (int i = 0; i < 64; ++i) acc += Cp[(size_t)i * DS];
        sh_part[s][d] = acc;
    }
    __syncthreads();
    if (tid < DS) {
        float t = 0.f;
        #pragma unroll
        for (int s2 = 0; s2 < 16; ++s2) t += sh_part[s2][tid];
        sh_csum[tid] = t;
    }
    __syncthreads();

    // phase B: 64 threads build K for channels blockIdx.x*64 .. +63
    if (tid < DS) {
        const int c = blockIdx.x * 64 + tid;
        const float dt = expf(log_dt[c]);

        float2 k2[LTAPS / 2];
        #pragma unroll
        for (int i = 0; i < LTAPS / 2; ++i) k2[i] = make_float2(0.f, 0.f);

        #pragma unroll 4
        for (int dd = 0; dd < DS; ++dd) {
            const float w  = sh_csum[dd] * Bp[(size_t)dd * DM + c];
            const float r  = expf(A[dd] * dt);
            const float r2 = r * r;
            float2 p = make_float2(w, w * r);
            const float2 rr = make_float2(r2, r2);
            #pragma unroll
            for (int i = 0; i < LTAPS / 2; ++i) {
                k2[i].x += p.x;
                k2[i].y += p.y;
                p = fmul2(p, rr);
            }
        }

        #pragma unroll
        for (int i = 0; i < LTAPS / 2; ++i) {
            g_K[(size_t)(2 * i)     * DM + c] = k2[i].x;
            g_K[(size_t)(2 * i + 1) * DM + c] = k2[i].y;
        }
    }
}

// ---------------- conv kernel: NO shared memory (R14-measured, verbatim) ------
// y[b,t,c] = D[c]*u[b,t,c] + sum_{l=0}^{63} K[l,c] * u[b, t+31-l, c]
// 512 threads: 32 channel-pairs x 16 time groups x TT=8 outputs.
// Window reads straight from global (coalesced 256B per warp, L1-hit after
// first touch across overlapping warps). No tile fill, no barrier.

template <bool SAFE>
__device__ __forceinline__ void conv_body(const float2* __restrict__ uw,
                                          const float2* __restrict__ Kp,
                                          float2 d2, int gt0,
                                          float2* __restrict__ yw) {
    auto ld = [&](int off) -> float2 {
        if (SAFE) {
            int t = gt0 + off;
            if (t < 0 || t >= SEQ) return make_float2(0.f, 0.f);
        }
        return __ldg(uw + (ptrdiff_t)off * (DM / 2));
    };

    float2 acc[TT];
    #pragma unroll
    for (int j = 0; j < TT; ++j)
        acc[j] = fmul2(d2, ld(j));

    float2 w[TT + G - 1];
    const int wb0 = 32 - G;   // = 24
    #pragma unroll
    for (int i = 0; i < TT + G - 1; ++i) w[i] = ld(wb0 + i);

    #pragma unroll
    for (int g = 0; g < LTAPS / G; ++g) {
        if (g > 0) {
            #pragma unroll
            for (int i = TT + G - 2; i >= G; --i) w[i] = w[i - G];
            const int wb = wb0 - g * G;
            #pragma unroll
            for (int i = 0; i < G; ++i) w[i] = ld(wb + i);
        }
        #pragma unroll
        for (int e = 0; e < G; ++e) {
            const int l = g * G + e;
            float2 k2 = Kp[(size_t)l * (DM / 2)];
            #pragma unroll
            for (int j = 0; j < TT; ++j)
                acc[j] = ffma2(k2, w[j + (G - 1 - e)], acc[j]);
        }
    }

    #pragma unroll
    for (int j = 0; j < TT; ++j)
        yw[(ptrdiff_t)j * (DM / 2)] = acc[j];
}

__global__ __launch_bounds__(NTHR, 2)
void conv_kernel(const float* __restrict__ u,
                 const float* __restrict__ Dp,
                 float* __restrict__ y) {
    const int b  = blockIdx.z;
    const int t0 = blockIdx.x * TBLK;
    const int c0 = blockIdx.y * CBLK;
    const int tid = threadIdx.x;

    const int p   = tid & 31;          // channel pair
    const int tg  = tid >> 5;          // time group (0..15)
    const int gt0 = t0 + tg * TT;      // global time of output j=0

    const float2* __restrict__ uw =
        reinterpret_cast<const float2*>(u + (size_t)b * SEQ * DM + c0)
        + (size_t)gt0 * (DM / 2) + p;

    const float2* __restrict__ Kp =
        reinterpret_cast<const float2*>(g_K) + (c0 >> 1) + p;

    const float2 d2 = reinterpret_cast<const float2*>(Dp + c0)[p];

    float2* __restrict__ yw =
        reinterpret_cast<float2*>(y + (size_t)b * SEQ * DM + c0)
        + (size_t)gt0 * (DM / 2) + p;

    if (t0 >= 32 && t0 + TBLK + 39 <= SEQ) {
        conv_body<false>(uw, Kp, d2, gt0, yw);
    } else {
        conv_body<true>(uw, Kp, d2, gt0, yw);
    }
}

// ---------------- launch ----------------

extern "C" void kernel_launch(void* const* d_in, const int* in_sizes, int n_in,
                              void* d_out, int out_size) {
    const float* u      = (const float*)d_in[0];
    const float* A      = (const float*)d_in[1];
    const float* Bp     = (const float*)d_in[2];
    const float* C      = (const float*)d_in[3];
    const float* Dp     = (const float*)d_in[4];
    const float* log_dt = (const float*)d_in[5];
    float* y = (float*)d_out;

    prep_kernel<<<16, 1024>>>(A, Bp, C, log_dt);

    dim3 grid(SEQ / TBLK, DM / CBLK, B_SZ);  // (32, 16, 8)
    conv_kernel<<<grid, NTHR>>>(u, Dp, y);
}

// round 16
// speedup vs baseline: 1.0135x; 1.0135x over previous
#include <cuda_runtime.h>
#include <cstdint>

#define B_SZ 8
#define SEQ 4096
#define DM 1024
#define DS 64
#define LTAPS 64

#define TBLK 128   // time steps per block
#define CBLK 64    // channels per block (32 float2 pairs)
#define TT 8       // outputs per thread
#define NTHR 512   // conv block size
#define G 8        // tap group size

__device__ float g_K[LTAPS * DM];   // K[l][c], channel-contiguous

// ---------------- packed f32x2 ops (Blackwell FFMA2, PTX-only) ----------------

__device__ __forceinline__ float2 ffma2(float2 a, float2 b, float2 c) {
    float2 d;
    asm("fma.rn.f32x2 %0, %1, %2, %3;"
        : "=l"(*reinterpret_cast<unsigned long long*>(&d))
        : "l"(*reinterpret_cast<const unsigned long long*>(&a)),
          "l"(*reinterpret_cast<const unsigned long long*>(&b)),
          "l"(*reinterpret_cast<const unsigned long long*>(&c)));
    return d;
}

__device__ __forceinline__ float2 fmul2(float2 a, float2 b) {
    float2 d;
    asm("mul.rn.f32x2 %0, %1, %2;"
        : "=l"(*reinterpret_cast<unsigned long long*>(&d))
        : "l"(*reinterpret_cast<const unsigned long long*>(&a)),
          "l"(*reinterpret_cast<const unsigned long long*>(&b)));
    return d;
}

// ---------------- fused prep: Csum + K build (spill-free phase B) -------------
// grid 16 x block 1024.
// Phase A: 16 slices x 64 cols, fully coalesced partial sums, smem reduce.
// Phase B: 256 threads; thread (c, q) builds taps [16q, 16q+16) of channel c
//          -> k2[8] float2 = 16 regs, no spills, 4x chain parallelism.
__global__ __launch_bounds__(1024)
void prep_kernel(const float* __restrict__ A,
                 const float* __restrict__ Bp,
                 const float* __restrict__ C,
                 const float* __restrict__ log_dt) {
    __shared__ float sh_part[16][DS];
    __shared__ float sh_csum[DS];

    const int tid = threadIdx.x;

    // phase A
    {
        const int d = tid & 63;
        const int s = tid >> 6;    // slice 0..15, rows [64s, 64s+64)
        const float* __restrict__ Cp = C + (size_t)(s * 64) * DS + d;
        float acc = 0.f;
        #pragma unroll 8
        for (int i = 0; i < 64; ++i) acc += Cp[(size_t)i * DS];
        sh_part[s][d] = acc;
    }
    __syncthreads();
    if (tid < DS) {
        float t = 0.f;
        #pragma unroll
        for (int s2 = 0; s2 < 16; ++s2) t += sh_part[s2][tid];
        sh_csum[tid] = t;
    }
    __syncthreads();

    // phase B: 256 threads
    if (tid < 256) {
        const int c = blockIdx.x * 64 + (tid & 63);
        const int q = tid >> 6;              // tap quarter 0..3
        const float q16 = (float)(16 * q);
        const float dt = expf(log_dt[c]);

        float2 k2[8];                         // taps 16q+2i, 16q+2i+1
        #pragma unroll
        for (int i = 0; i < 8; ++i) k2[i] = make_float2(0.f, 0.f);

        #pragma unroll 2
        for (int dd = 0; dd < DS; ++dd) {
            const float w  = sh_csum[dd] * Bp[(size_t)dd * DM + c];
            const float a  = A[dd] * dt;
            const float r  = expf(a);
            const float rs = expf(a * q16);   // r^(16q)
            const float r2 = r * r;
            float2 p = make_float2(w * rs, w * rs * r);
            const float2 rr = make_float2(r2, r2);
            #pragma unroll
            for (int i = 0; i < 8; ++i) {
                k2[i].x += p.x;
                k2[i].y += p.y;
                p = fmul2(p, rr);
            }
        }

        #pragma unroll
        for (int i = 0; i < 8; ++i) {
            g_K[(size_t)(16 * q + 2 * i)     * DM + c] = k2[i].x;
            g_K[(size_t)(16 * q + 2 * i + 1) * DM + c] = k2[i].y;
        }
    }
}

// ---------------- conv kernel: NO shared memory (R14-measured, verbatim) ------
// y[b,t,c] = D[c]*u[b,t,c] + sum_{l=0}^{63} K[l,c] * u[b, t+31-l, c]
// 512 threads: 32 channel-pairs x 16 time groups x TT=8 outputs.

template <bool SAFE>
__device__ __forceinline__ void conv_body(const float2* __restrict__ uw,
                                          const float2* __restrict__ Kp,
                                          float2 d2, int gt0,
                                          float2* __restrict__ yw) {
    auto ld = [&](int off) -> float2 {
        if (SAFE) {
            int t = gt0 + off;
            if (t < 0 || t >= SEQ) return make_float2(0.f, 0.f);
        }
        return __ldg(uw + (ptrdiff_t)off * (DM / 2));
    };

    float2 acc[TT];
    #pragma unroll
    for (int j = 0; j < TT; ++j)
        acc[j] = fmul2(d2, ld(j));

    float2 w[TT + G - 1];
    const int wb0 = 32 - G;   // = 24
    #pragma unroll
    for (int i = 0; i < TT + G - 1; ++i) w[i] = ld(wb0 + i);

    #pragma unroll
    for (int g = 0; g < LTAPS / G; ++g) {
        if (g > 0) {
            #pragma unroll
            for (int i = TT + G - 2; i >= G; --i) w[i] = w[i - G];
            const int wb = wb0 - g * G;
            #pragma unroll
            for (int i = 0; i < G; ++i) w[i] = ld(wb + i);
        }
        #pragma unroll
        for (int e = 0; e < G; ++e) {
            const int l = g * G + e;
            float2 k2 = Kp[(size_t)l * (DM / 2)];
            #pragma unroll
            for (int j = 0; j < TT; ++j)
                acc[j] = ffma2(k2, w[j + (G - 1 - e)], acc[j]);
        }
    }

    #pragma unroll
    for (int j = 0; j < TT; ++j)
        yw[(ptrdiff_t)j * (DM / 2)] = acc[j];
}

__global__ __launch_bounds__(NTHR, 2)
void conv_kernel(const float* __restrict__ u,
                 const float* __restrict__ Dp,
                 float* __restrict__ y) {
    const int b  = blockIdx.z;
    const int t0 = blockIdx.x * TBLK;
    const int c0 = blockIdx.y * CBLK;
    const int tid = threadIdx.x;

    const int p   = tid & 31;          // channel pair
    const int tg  = tid >> 5;          // time group (0..15)
    const int gt0 = t0 + tg * TT;      // global time of output j=0

    const float2* __restrict__ uw =
        reinterpret_cast<const float2*>(u + (size_t)b * SEQ * DM + c0)
        + (size_t)gt0 * (DM / 2) + p;

    const float2* __restrict__ Kp =
        reinterpret_cast<const float2*>(g_K) + (c0 >> 1) + p;

    const float2 d2 = reinterpret_cast<const float2*>(Dp + c0)[p];

    float2* __restrict__ yw =
        reinterpret_cast<float2*>(y + (size_t)b * SEQ * DM + c0)
        + (size_t)gt0 * (DM / 2) + p;

    if (t0 >= 32 && t0 + TBLK + 39 <= SEQ) {
        conv_body<false>(uw, Kp, d2, gt0, yw);
    } else {
        conv_body<true>(uw, Kp, d2, gt0, yw);
    }
}

// ---------------- launch ----------------

extern "C" void kernel_launch(void* const* d_in, const int* in_sizes, int n_in,
                              void* d_out, int out_size) {
    const float* u      = (const float*)d_in[0];
    const float* A      = (const float*)d_in[1];
    const float* Bp     = (const float*)d_in[2];
    const float* C      = (const float*)d_in[3];
    const float* Dp     = (const float*)d_in[4];
    const float* log_dt = (const float*)d_in[5];
    float* y = (float*)d_out;

    prep_kernel<<<16, 1024>>>(A, Bp, C, log_dt);

    dim3 grid(SEQ / TBLK, DM / CBLK, B_SZ);  // (32, 16, 8)
    conv_kernel<<<grid, NTHR>>>(u, Dp, y);
}

// round 17
// speedup vs baseline: 1.1331x; 1.1180x over previous
#include <cuda_runtime.h>
#include <cstdint>

#define B_SZ 8
#define SEQ 4096
#define DM 1024
#define DS 64
#define LTAPS 64

#define TBLK 128   // time steps per block
#define CBLK 64    // channels per block (32 float2 pairs)
#define TT 8       // outputs per thread
#define NTHR 512   // conv block size
#define G 8        // tap group size

__device__ float g_part[128 * DS];  // partial C column sums
__device__ float g_K[LTAPS * DM];   // K[l][c], channel-contiguous

// ---------------- packed f32x2 ops (Blackwell FFMA2, PTX-only) ----------------

__device__ __forceinline__ float2 ffma2(float2 a, float2 b, float2 c) {
    float2 d;
    asm("fma.rn.f32x2 %0, %1, %2, %3;"
        : "=l"(*reinterpret_cast<unsigned long long*>(&d))
        : "l"(*reinterpret_cast<const unsigned long long*>(&a)),
          "l"(*reinterpret_cast<const unsigned long long*>(&b)),
          "l"(*reinterpret_cast<const unsigned long long*>(&c)));
    return d;
}

__device__ __forceinline__ float2 fmul2(float2 a, float2 b) {
    float2 d;
    asm("mul.rn.f32x2 %0, %1, %2;"
        : "=l"(*reinterpret_cast<unsigned long long*>(&d))
        : "l"(*reinterpret_cast<const unsigned long long*>(&a)),
          "l"(*reinterpret_cast<const unsigned long long*>(&b)));
    return d;
}

// ---------------- prep: stage A — partial column sums of C (coalesced) --------
// 128 blocks x 64 threads; block j reduces rows [8j, 8j+8).
__global__ __launch_bounds__(64)
void csum_part_kernel(const float* __restrict__ C) {
    const int d = threadIdx.x;
    const float* __restrict__ Cp = C + (size_t)blockIdx.x * 8 * DS + d;
    float s = 0.f;
    #pragma unroll
    for (int i = 0; i < 8; ++i) s += Cp[(size_t)i * DS];
    g_part[blockIdx.x * DS + d] = s;
}

// ---------------- prep: stage B + K build (quartered tap chains) --------------
// grid 16 x block 256; thread (c, q) builds taps [16q, 16q+16) of channel c.
__global__ __launch_bounds__(256)
void kbuild_kernel(const float* __restrict__ A,
                   const float* __restrict__ Bp,
                   const float* __restrict__ log_dt) {
    __shared__ float sh_csum[DS];
    const int tid = threadIdx.x;

    if (tid < DS) {
        float s = 0.f;
        #pragma unroll 16
        for (int j = 0; j < 128; ++j) s += g_part[j * DS + tid];
        sh_csum[tid] = s;
    }
    __syncthreads();

    const int c = blockIdx.x * 64 + (tid & 63);
    const int q = tid >> 6;              // tap quarter 0..3
    const float q16 = (float)(16 * q);
    const float dt = expf(log_dt[c]);

    float2 k2[8];                         // taps 16q+2i, 16q+2i+1
    #pragma unroll
    for (int i = 0; i < 8; ++i) k2[i] = make_float2(0.f, 0.f);

    #pragma unroll 2
    for (int dd = 0; dd < DS; ++dd) {
        const float w  = sh_csum[dd] * Bp[(size_t)dd * DM + c];
        const float a  = A[dd] * dt;
        const float r  = expf(a);
        const float rs = expf(a * q16);   // r^(16q)
        const float r2 = r * r;
        float2 p = make_float2(w * rs, w * rs * r);
        const float2 rr = make_float2(r2, r2);
        #pragma unroll
        for (int i = 0; i < 8; ++i) {
            k2[i].x += p.x;
            k2[i].y += p.y;
            p = fmul2(p, rr);
        }
    }

    #pragma unroll
    for (int i = 0; i < 8; ++i) {
        g_K[(size_t)(16 * q + 2 * i)     * DM + c] = k2[i].x;
        g_K[(size_t)(16 * q + 2 * i + 1) * DM + c] = k2[i].y;
    }
}

// ---------------- conv kernel: NO shared memory (R14-measured, verbatim) ------
// y[b,t,c] = D[c]*u[b,t,c] + sum_{l=0}^{63} K[l,c] * u[b, t+31-l, c]
// 512 threads: 32 channel-pairs x 16 time groups x TT=8 outputs.
// Window reads straight from global (coalesced 256B per warp, L1-hit after
// first touch across overlapping warps). No tile fill, no barrier.

template <bool SAFE>
__device__ __forceinline__ void conv_body(const float2* __restrict__ uw,
                                          const float2* __restrict__ Kp,
                                          float2 d2, int gt0,
                                          float2* __restrict__ yw) {
    auto ld = [&](int off) -> float2 {
        if (SAFE) {
            int t = gt0 + off;
            if (t < 0 || t >= SEQ) return make_float2(0.f, 0.f);
        }
        return __ldg(uw + (ptrdiff_t)off * (DM / 2));
    };

    float2 acc[TT];
    #pragma unroll
    for (int j = 0; j < TT; ++j)
        acc[j] = fmul2(d2, ld(j));

    float2 w[TT + G - 1];
    const int wb0 = 32 - G;   // = 24
    #pragma unroll
    for (int i = 0; i < TT + G - 1; ++i) w[i] = ld(wb0 + i);

    #pragma unroll
    for (int g = 0; g < LTAPS / G; ++g) {
        if (g > 0) {
            #pragma unroll
            for (int i = TT + G - 2; i >= G; --i) w[i] = w[i - G];
            const int wb = wb0 - g * G;
            #pragma unroll
            for (int i = 0; i < G; ++i) w[i] = ld(wb + i);
        }
        #pragma unroll
        for (int e = 0; e < G; ++e) {
            const int l = g * G + e;
            float2 k2 = Kp[(size_t)l * (DM / 2)];
            #pragma unroll
            for (int j = 0; j < TT; ++j)
                acc[j] = ffma2(k2, w[j + (G - 1 - e)], acc[j]);
        }
    }

    #pragma unroll
    for (int j = 0; j < TT; ++j)
        yw[(ptrdiff_t)j * (DM / 2)] = acc[j];
}

__global__ __launch_bounds__(NTHR, 2)
void conv_kernel(const float* __restrict__ u,
                 const float* __restrict__ Dp,
                 float* __restrict__ y) {
    const int b  = blockIdx.z;
    const int t0 = blockIdx.x * TBLK;
    const int c0 = blockIdx.y * CBLK;
    const int tid = threadIdx.x;

    const int p   = tid & 31;          // channel pair
    const int tg  = tid >> 5;          // time group (0..15)
    const int gt0 = t0 + tg * TT;      // global time of output j=0

    const float2* __restrict__ uw =
        reinterpret_cast<const float2*>(u + (size_t)b * SEQ * DM + c0)
        + (size_t)gt0 * (DM / 2) + p;

    const float2* __restrict__ Kp =
        reinterpret_cast<const float2*>(g_K) + (c0 >> 1) + p;

    const float2 d2 = reinterpret_cast<const float2*>(Dp + c0)[p];

    float2* __restrict__ yw =
        reinterpret_cast<float2*>(y + (size_t)b * SEQ * DM + c0)
        + (size_t)gt0 * (DM / 2) + p;

    if (t0 >= 32 && t0 + TBLK + 39 <= SEQ) {
        conv_body<false>(uw, Kp, d2, gt0, yw);
    } else {
        conv_body<true>(uw, Kp, d2, gt0, yw);
    }
}

// ---------------- launch ----------------

extern "C" void kernel_launch(void* const* d_in, const int* in_sizes, int n_in,
                              void* d_out, int out_size) {
    const float* u      = (const float*)d_in[0];
    const float* A      = (const float*)d_in[1];
    const float* Bp     = (const float*)d_in[2];
    const float* C      = (const float*)d_in[3];
    const float* Dp     = (const float*)d_in[4];
    const float* log_dt = (const float*)d_in[5];
    float* y = (float*)d_out;

    csum_part_kernel<<<128, 64>>>(C);
    kbuild_kernel<<<16, 256>>>(A, Bp, log_dt);

    dim3 grid(SEQ / TBLK, DM / CBLK, B_SZ);  // (32, 16, 8)
    conv_kernel<<<grid, NTHR>>>(u, Dp, y);
}